// round 11
// baseline (speedup 1.0000x reference)
#include <cuda_runtime.h>
#include <cuda_bf16.h>
#include <cstdint>

#define BB 8
#define SS 1024
#define EE 512
#define HH 8
#define HE 4096
#define MQ 8192

#define BM 128
#define BN 128

typedef __nv_bfloat16 bf;

// fp32 scratch
__device__ float g_E [(size_t)BB * HH * SS * SS];
__device__ float g_Pv[(size_t)MQ * HE];
// bf16 hi/lo planes
__device__ bf g_qH [(size_t)MQ*EE], g_qL [(size_t)MQ*EE];
__device__ bf g_kH [(size_t)MQ*EE], g_kL [(size_t)MQ*EE];
__device__ bf g_vH [(size_t)MQ*EE], g_vL [(size_t)MQ*EE];
__device__ bf g_WqH[(size_t)HE*EE], g_WqL[(size_t)HE*EE];
__device__ bf g_WkH[(size_t)HE*EE], g_WkL[(size_t)HE*EE];
__device__ bf g_WvH[(size_t)HE*EE], g_WvL[(size_t)HE*EE];
__device__ bf g_WoH[(size_t)EE*HE], g_WoL[(size_t)EE*HE];
__device__ bf g_PqH[(size_t)MQ*HE], g_PqL[(size_t)MQ*HE];
__device__ bf g_PkH[(size_t)MQ*HE], g_PkL[(size_t)MQ*HE];
__device__ bf g_PH [(size_t)BB*HH*SS*SS], g_PL[(size_t)BB*HH*SS*SS];
__device__ bf g_FH [(size_t)MQ*HE], g_FL [(size_t)MQ*HE];

__device__ __forceinline__ void sp1(float f, uint16_t& h, uint16_t& l) {
    bf hb = __float2bfloat16(f);
    bf lb = __float2bfloat16(f - __bfloat162float(hb));
    h = __bfloat16_as_ushort(hb); l = __bfloat16_as_ushort(lb);
}
__device__ __forceinline__ uint32_t pkhl(float a, float b, uint32_t& lo) {
    uint16_t ha, la, hb2, lb2;
    sp1(a, ha, la); sp1(b, hb2, lb2);
    lo = ((uint32_t)lb2 << 16) | la;
    return ((uint32_t)hb2 << 16) | ha;
}

#define MMA16(acc, a, b) \
    asm volatile("mma.sync.aligned.m16n8k16.row.col.f32.bf16.bf16.f32 " \
        "{%0,%1,%2,%3},{%4,%5,%6,%7},{%8,%9},{%0,%1,%2,%3};" \
        : "+f"((acc)[0]), "+f"((acc)[1]), "+f"((acc)[2]), "+f"((acc)[3]) \
        : "r"((a)[0]), "r"((a)[1]), "r"((a)[2]), "r"((a)[3]), \
          "r"((b)[0]), "r"((b)[1]))

// ---------------------------------------------------------------------------
// Pre-split: fp32 -> hi/lo bf16 planes
// ---------------------------------------------------------------------------
__global__ void k_split(const float* __restrict__ in, bf* __restrict__ H,
                        bf* __restrict__ L, int n4)
{
    int i = blockIdx.x * 256 + threadIdx.x;
    if (i >= n4) return;
    float4 v = ((const float4*)in)[i];
    uint2 h, l;
    h.x = pkhl(v.x, v.y, l.x);
    h.y = pkhl(v.z, v.w, l.y);
    ((uint2*)H)[i] = h;
    ((uint2*)L)[i] = l;
}

// ---------------------------------------------------------------------------
// C[128,128] = A @ op(B), bf16x3 emulated fp32 on m16n8k16.
// A from planes always. BMODE 0: B from planes (NT). BMODE 1: B fp32 [K,N],
// transposed+split on smem store (R8-proven path).
// EPI 0: hi/lo plane out. EPI 1: fp32. EPI 2: fp32+bias.
// Smem planes: 128 rows x 8 u32 words; 16B-unit flip on (row & 4).
// ---------------------------------------------------------------------------
template<int BMODE, int EPI>
__device__ __forceinline__ void mma_tile(
    const bf* __restrict__ AH, const bf* __restrict__ AL, int lda,
    const bf* __restrict__ BH, const bf* __restrict__ BL,
    const float* __restrict__ Bf, int ldb,
    void* O0, void* O1, int ldc,
    int K, int m0, int n0, const float* __restrict__ bias)
{
    __shared__ uint32_t AsH[4][BM * 8], AsL[4][BM * 8];
    __shared__ uint32_t BsH[4][BN * 8], BsL[4][BN * 8];

    const int tid  = threadIdx.x;
    const int wid  = tid >> 5;
    const int lane = tid & 31;
    const int wm   = wid & 1;      // 2x4 warp grid; warp tile 64x32
    const int wn   = wid >> 1;
    const int qr   = lane >> 2;
    const int qc   = lane & 3;
    const int swz  = qr & 4;

    const int arow = tid >> 2;     // 0..63 (+64 second chunk)
    const int ak4  = tid & 3;
    const int bk   = tid & 15;     // BMODE 1 path
    const int bn4  = tid >> 4;

    float acc[4][4][4];
#pragma unroll
    for (int i = 0; i < 4; ++i)
#pragma unroll
        for (int j = 0; j < 4; ++j)
#pragma unroll
            for (int r = 0; r < 4; ++r) acc[i][j][r] = 0.0f;

    uint2 aH0, aL0, aH1, aL1, bH0, bL0, bH1, bL1;
    float4 br0, br1;

    auto load_g = [&](int k0) {
        const size_t a0 = (size_t)(m0 + arow) * lda + k0 + ak4 * 4;
        const size_t a1 = a0 + (size_t)64 * lda;
        aH0 = *(const uint2*)(AH + a0);  aL0 = *(const uint2*)(AL + a0);
        aH1 = *(const uint2*)(AH + a1);  aL1 = *(const uint2*)(AL + a1);
        if (BMODE == 0) {
            const size_t b0 = (size_t)(n0 + arow) * ldb + k0 + ak4 * 4;
            const size_t b1 = b0 + (size_t)64 * ldb;
            bH0 = *(const uint2*)(BH + b0);  bL0 = *(const uint2*)(BL + b0);
            bH1 = *(const uint2*)(BH + b1);  bL1 = *(const uint2*)(BL + b1);
        } else {
            const float* bp = Bf + (size_t)(k0 + bk) * ldb + n0 + bn4 * 4;
            br0 = *(const float4*)bp;
            br1 = *(const float4*)(bp + 64);
        }
    };

    auto store_s = [&](int bu) {
        const int w0  = (ak4 * 2) ^ ((arow & 4) ? 4 : 0);
        const int w0b = (ak4 * 2) ^ (((arow + 64) & 4) ? 4 : 0);
        *(uint2*)&AsH[bu][arow * 8 + w0] = aH0;
        *(uint2*)&AsL[bu][arow * 8 + w0] = aL0;
        *(uint2*)&AsH[bu][(arow + 64) * 8 + w0b] = aH1;
        *(uint2*)&AsL[bu][(arow + 64) * 8 + w0b] = aL1;
        if (BMODE == 0) {
            *(uint2*)&BsH[bu][arow * 8 + w0] = bH0;
            *(uint2*)&BsL[bu][arow * 8 + w0] = bL0;
            *(uint2*)&BsH[bu][(arow + 64) * 8 + w0b] = bH1;
            *(uint2*)&BsL[bu][(arow + 64) * 8 + w0b] = bL1;
        } else {
            const int wd = bk >> 1, hf = bk & 1;
            const float* s0 = &br0.x;
            const float* s1 = &br1.x;
#pragma unroll
            for (int j = 0; j < 4; ++j) {
                int r0 = bn4 * 4 + j, r1 = r0 + 64;
                int p0 = r0 * 8 + (wd ^ ((r0 & 4) ? 4 : 0));
                int p1 = r1 * 8 + (wd ^ ((r1 & 4) ? 4 : 0));
                uint16_t h, l;
                sp1(s0[j], h, l);
                ((uint16_t*)&BsH[bu][p0])[hf] = h;
                ((uint16_t*)&BsL[bu][p0])[hf] = l;
                sp1(s1[j], h, l);
                ((uint16_t*)&BsH[bu][p1])[hf] = h;
                ((uint16_t*)&BsL[bu][p1])[hf] = l;
            }
        }
    };

    auto compute = [&](int bu) {
        const int wA = qc ^ swz, wA2 = (qc + 4) ^ swz;
        uint32_t bh[4][2], bl[4][2];
#pragma unroll
        for (int nt = 0; nt < 4; ++nt) {
            int rb = (wn * 32 + nt * 8 + qr) * 8;
            bh[nt][0] = BsH[bu][rb + wA];  bh[nt][1] = BsH[bu][rb + wA2];
            bl[nt][0] = BsL[bu][rb + wA];  bl[nt][1] = BsL[bu][rb + wA2];
        }
        {
            uint32_t a[4][4];
#pragma unroll
            for (int mt = 0; mt < 4; ++mt) {
                int ra = (wm * 64 + mt * 16 + qr) * 8;
                a[mt][0] = AsH[bu][ra + wA];   a[mt][1] = AsH[bu][ra + 64 + wA];
                a[mt][2] = AsH[bu][ra + wA2];  a[mt][3] = AsH[bu][ra + 64 + wA2];
            }
#pragma unroll
            for (int mt = 0; mt < 4; ++mt)
#pragma unroll
                for (int nt = 0; nt < 4; ++nt) {
                    MMA16(acc[mt][nt], a[mt], bh[nt]);
                    MMA16(acc[mt][nt], a[mt], bl[nt]);
                }
        }
        {
            uint32_t a[4][4];
#pragma unroll
            for (int mt = 0; mt < 4; ++mt) {
                int ra = (wm * 64 + mt * 16 + qr) * 8;
                a[mt][0] = AsL[bu][ra + wA];   a[mt][1] = AsL[bu][ra + 64 + wA];
                a[mt][2] = AsL[bu][ra + wA2];  a[mt][3] = AsL[bu][ra + 64 + wA2];
            }
#pragma unroll
            for (int mt = 0; mt < 4; ++mt)
#pragma unroll
                for (int nt = 0; nt < 4; ++nt)
                    MMA16(acc[mt][nt], a[mt], bh[nt]);
        }
    };

    // k32 pipeline: one barrier per 32-k (R8-proven)
    const int nkc = K >> 5;
    load_g(0);  store_s(0);
    load_g(16); store_s(1);
    __syncthreads();
    for (int kc = 1; kc < nkc; ++kc) {
        const int st = (kc & 1) * 2;
        const int pv = ((kc - 1) & 1) * 2;
        load_g(kc * 32);
        compute(pv);
        store_s(st);
        load_g(kc * 32 + 16);
        compute(pv + 1);
        store_s(st + 1);
        __syncthreads();
    }
    const int lp = ((nkc - 1) & 1) * 2;
    compute(lp);
    compute(lp + 1);

    // ---------------- epilogues ----------------
    if (EPI == 1 || EPI == 2) {
        float* C = (float*)O0;
#pragma unroll
        for (int mt = 0; mt < 4; ++mt)
#pragma unroll
            for (int nt = 0; nt < 4; ++nt) {
                int row = m0 + wm * 64 + mt * 16 + qr;
                int col = n0 + wn * 32 + nt * 8 + qc * 2;
                float2 v0, v1;
                v0.x = acc[mt][nt][0]; v0.y = acc[mt][nt][1];
                v1.x = acc[mt][nt][2]; v1.y = acc[mt][nt][3];
                if (EPI == 2) {
                    v0.x += bias[col]; v0.y += bias[col + 1];
                    v1.x += bias[col]; v1.y += bias[col + 1];
                }
                *(float2*)&C[(size_t)row * ldc + col] = v0;
                *(float2*)&C[(size_t)(row + 8) * ldc + col] = v1;
            }
    } else {
        bf* CH = (bf*)O0;
        bf* CL = (bf*)O1;
#pragma unroll
        for (int mt = 0; mt < 4; ++mt)
#pragma unroll
            for (int nt = 0; nt < 4; ++nt) {
                int row = m0 + wm * 64 + mt * 16 + qr;
                int col = n0 + wn * 32 + nt * 8 + qc * 2;
                uint32_t l0, l1;
                uint32_t h0 = pkhl(acc[mt][nt][0], acc[mt][nt][1], l0);
                uint32_t h1 = pkhl(acc[mt][nt][2], acc[mt][nt][3], l1);
                *(uint32_t*)&CH[(size_t)row * ldc + col] = h0;
                *(uint32_t*)&CL[(size_t)row * ldc + col] = l0;
                *(uint32_t*)&CH[(size_t)(row + 8) * ldc + col] = h1;
                *(uint32_t*)&CL[(size_t)(row + 8) * ldc + col] = l1;
            }
    }
}

// ---------------------------------------------------------------------------
__global__ void __launch_bounds__(256, 2)
k_proj(const bf* AH, const bf* AL, const bf* BH, const bf* BL,
       bf* CH, bf* CL)
{
    mma_tile<0, 0>(AH, AL, EE, BH, BL, nullptr, EE, CH, CL, HE, EE,
                   blockIdx.y * BM, blockIdx.x * BN, nullptr);
}
__global__ void __launch_bounds__(256, 2)
k_projv(const bf* AH, const bf* AL, const bf* BH, const bf* BL, float* C)
{
    mma_tile<0, 1>(AH, AL, EE, BH, BL, nullptr, EE, C, nullptr, HE, EE,
                   blockIdx.y * BM, blockIdx.x * BN, nullptr);
}
__global__ void __launch_bounds__(256, 2)
k_energy(const bf* PqH, const bf* PqL, const bf* PkH, const bf* PkL,
         float* E)
{
    const int bh = blockIdx.z, m0 = blockIdx.y * BM, n0 = blockIdx.x * BN;
    if (n0 > m0) return;
    const size_t o = (size_t)bh * SS * EE;
    mma_tile<0, 1>(PqH + o, PqL + o, EE, PkH + o, PkL + o, nullptr, EE,
                   E + (size_t)bh * SS * SS, nullptr, SS, EE, m0, n0, nullptr);
}
__global__ void __launch_bounds__(256, 2)
k_pv(const bf* PH, const bf* PL, const float* Pv, bf* FH, bf* FL)
{
    const int bh = blockIdx.z, b = bh >> 3, h = bh & 7;
    const int m0 = blockIdx.y * BM, n0 = blockIdx.x * BN;
    const size_t op = (size_t)bh * SS * SS;
    const size_t ov = (size_t)bh * SS * EE;
    const size_t of = (size_t)b * SS * HE + (size_t)h * EE;
    mma_tile<1, 0>(PH + op, PL + op, SS, nullptr, nullptr, Pv + ov, EE,
                   FH + of, FL + of, HE, m0 + BM, m0, n0, nullptr);
}
__global__ void __launch_bounds__(256, 2)
k_outp(const bf* FH, const bf* FL, const bf* WoH, const bf* WoL,
       float* C, const float* bias)
{
    mma_tile<0, 2>(FH, FL, HE, WoH, WoL, nullptr, HE, C, nullptr, EE, HE,
                   blockIdx.y * BM, blockIdx.x * BN, bias);
}

// Causal softmax: fp32 E in, hi/lo P planes out (mask-before-scale, 1/8)
__global__ void k_softmax(const float* __restrict__ E,
                          bf* __restrict__ PH, bf* __restrict__ PL)
{
    const int i = blockIdx.x;
    const size_t roff = ((size_t)blockIdx.y * SS + i) * SS;
    const int L = i + 1;
    const int tid = threadIdx.x;

    float r[4];
    float lmax = -1e30f;
#pragma unroll
    for (int t = 0; t < 4; ++t) {
        int j = tid + t * 256;
        if (j < L) { r[t] = E[roff + j]; lmax = fmaxf(lmax, r[t]); }
        else         r[t] = -1e30f;
    }
    __shared__ float red[8];
    for (int o = 16; o; o >>= 1) lmax = fmaxf(lmax, __shfl_xor_sync(0xffffffffu, lmax, o));
    if ((tid & 31) == 0) red[tid >> 5] = lmax;
    __syncthreads();
    if (tid == 0) {
        float m = red[0];
#pragma unroll
        for (int w = 1; w < 8; ++w) m = fmaxf(m, red[w]);
        red[0] = m;
    }
    __syncthreads();
    const float m = red[0];
    __syncthreads();

    float lsum = 0.0f;
#pragma unroll
    for (int t = 0; t < 4; ++t) {
        int j = tid + t * 256;
        if (j < L) { r[t] = __expf((r[t] - m) * 0.125f); lsum += r[t]; }
        else         r[t] = 0.0f;
    }
    for (int o = 16; o; o >>= 1) lsum += __shfl_xor_sync(0xffffffffu, lsum, o);
    if ((tid & 31) == 0) red[tid >> 5] = lsum;
    __syncthreads();
    if (tid == 0) {
        float s = red[0];
#pragma unroll
        for (int w = 1; w < 8; ++w) s += red[w];
        red[0] = s;
    }
    __syncthreads();
    const float inv = 1.0f / red[0];
#pragma unroll
    for (int t = 0; t < 4; ++t) {
        int j = tid + t * 256;
        uint16_t h, l;
        sp1(r[t] * inv, h, l);
        ((uint16_t*)PH)[roff + j] = h;
        ((uint16_t*)PL)[roff + j] = l;
    }
}

// ---------------------------------------------------------------------------
extern "C" void kernel_launch(void* const* d_in, const int* in_sizes, int n_in,
                              void* d_out, int out_size)
{
    (void)in_sizes; (void)n_in; (void)out_size;
    const float* k  = (const float*)d_in[0];
    const float* v  = (const float*)d_in[1];
    const float* q  = (const float*)d_in[2];
    const float* Wk = (const float*)d_in[4];
    const float* Wq = (const float*)d_in[5];
    const float* Wv = (const float*)d_in[6];
    const float* Wo = (const float*)d_in[7];
    const float* bo = (const float*)d_in[8];
    float* out = (float*)d_out;

    float *E, *Pv;
    cudaGetSymbolAddress((void**)&E,  g_E);
    cudaGetSymbolAddress((void**)&Pv, g_Pv);
#define GA(p, s) bf* p; cudaGetSymbolAddress((void**)&p, s)
    GA(qH, g_qH);   GA(qL, g_qL);   GA(kH, g_kH);   GA(kL, g_kL);
    GA(vH, g_vH);   GA(vL, g_vL);
    GA(WqH, g_WqH); GA(WqL, g_WqL); GA(WkH, g_WkH); GA(WkL, g_WkL);
    GA(WvH, g_WvH); GA(WvL, g_WvL); GA(WoH, g_WoH); GA(WoL, g_WoL);
    GA(PqH, g_PqH); GA(PqL, g_PqL); GA(PkH, g_PkH); GA(PkL, g_PkL);
    GA(PH, g_PH);   GA(PL, g_PL);
    GA(FH, g_FH);   GA(FL, g_FL);
#undef GA

    dim3 blk(256);

    const int nIn4 = (MQ * EE) / 4, nW4 = (HE * EE) / 4;
    k_split<<<(nIn4 + 255) / 256, blk>>>(q,  qH,  qL,  nIn4);
    k_split<<<(nIn4 + 255) / 256, blk>>>(k,  kH,  kL,  nIn4);
    k_split<<<(nIn4 + 255) / 256, blk>>>(v,  vH,  vL,  nIn4);
    k_split<<<(nW4 + 255) / 256, blk>>>(Wq, WqH, WqL, nW4);
    k_split<<<(nW4 + 255) / 256, blk>>>(Wk, WkH, WkL, nW4);
    k_split<<<(nW4 + 255) / 256, blk>>>(Wv, WvH, WvL, nW4);
    k_split<<<(nW4 + 255) / 256, blk>>>(Wo, WoH, WoL, nW4);

    dim3 gp(HE / BN, MQ / BM);
    k_proj <<<gp, blk>>>(qH, qL, WqH, WqL, PqH, PqL);
    k_proj <<<gp, blk>>>(kH, kL, WkH, WkL, PkH, PkL);
    k_projv<<<gp, blk>>>(vH, vL, WvH, WvL, Pv);

    dim3 ge(SS / BN, SS / BM, BB * HH);
    k_energy<<<ge, blk>>>(PqH, PqL, PkH, PkL, E);

    k_softmax<<<dim3(SS, BB * HH), 256>>>(E, PH, PL);

    dim3 gv(EE / BN, SS / BM, BB * HH);
    k_pv<<<gv, blk>>>(PH, PL, Pv, FH, FL);

    dim3 go(EE / BN, MQ / BM);
    k_outp<<<go, blk>>>(FH, FL, WoH, WoL, out, bo);
}

// round 12
// speedup vs baseline: 1.1061x; 1.1061x over previous
#include <cuda_runtime.h>
#include <cuda_bf16.h>
#include <cstdint>

#define BB 8
#define SS 1024
#define EE 512
#define HH 8
#define HE 4096
#define MQ 8192

#define BM 128
#define BN 128

__device__ float g_Pq[(size_t)MQ * HE];
__device__ float g_Pk[(size_t)MQ * HE];
__device__ float g_Pv[(size_t)MQ * HE];
__device__ float g_E [(size_t)BB * HH * SS * SS];
__device__ float g_F [(size_t)MQ * HE];

__device__ __forceinline__ uint32_t pk2(__nv_bfloat16 a, __nv_bfloat16 b) {
    return ((uint32_t)__bfloat16_as_ushort(b) << 16) | (uint32_t)__bfloat16_as_ushort(a);
}
__device__ __forceinline__ void split4(float4 v, uint2& hi, uint2& lo) {
    __nv_bfloat16 hx = __float2bfloat16(v.x), hy = __float2bfloat16(v.y);
    __nv_bfloat16 hz = __float2bfloat16(v.z), hw = __float2bfloat16(v.w);
    __nv_bfloat16 lx = __float2bfloat16(v.x - __bfloat162float(hx));
    __nv_bfloat16 ly = __float2bfloat16(v.y - __bfloat162float(hy));
    __nv_bfloat16 lz = __float2bfloat16(v.z - __bfloat162float(hz));
    __nv_bfloat16 lw = __float2bfloat16(v.w - __bfloat162float(hw));
    hi.x = pk2(hx, hy); hi.y = pk2(hz, hw);
    lo.x = pk2(lx, ly); lo.y = pk2(lz, lw);
}

#define MMA16(acc, a0, a1, a2, a3, b0, b1) \
    asm volatile("mma.sync.aligned.m16n8k16.row.col.f32.bf16.bf16.f32 " \
        "{%0,%1,%2,%3},{%4,%5,%6,%7},{%8,%9},{%0,%1,%2,%3};" \
        : "+f"((acc)[0]), "+f"((acc)[1]), "+f"((acc)[2]), "+f"((acc)[3]) \
        : "r"(a0), "r"(a1), "r"(a2), "r"(a3), "r"(b0), "r"(b1))

// ---------------------------------------------------------------------------
// C[128,128] = A[M,K] @ op(B), bf16x3 emulated fp32 on m16n8k16 tensor cores.
// Paired-word layout: orig word w -> pos (w<4 ? 2w : 2(w-4)+1), so fragment
// pairs (w, w+4) are adjacent -> LDS.64 loads, no swizzle needed.
// 4 k16 sub-buffers (2 stages x 2); one barrier per 32-k.
// ---------------------------------------------------------------------------
template<bool TRANSB, bool HASBIAS>
__device__ __forceinline__ void mma_tile(
    const float* __restrict__ A, int lda,
    const float* __restrict__ B, int ldb,
    float* __restrict__ C, int ldc,
    int K, int m0, int n0, const float* __restrict__ bias)
{
    __shared__ uint32_t AsH[4][BM * 8], AsL[4][BM * 8];
    __shared__ uint32_t BsH[4][BN * 8], BsL[4][BN * 8];

    const int tid  = threadIdx.x;
    const int wid  = tid >> 5;
    const int lane = tid & 31;
    const int wm   = wid & 1;      // 2x4 warp grid; warp tile 64x32
    const int wn   = wid >> 1;
    const int qr   = lane >> 2;
    const int qc   = lane & 3;

    const int arow = tid >> 2;     // 0..63 (+64 second chunk)
    const int ak4  = tid & 3;
    const int bk   = tid & 15;     // TRANSB path
    const int bn4  = tid >> 4;

    // store positions for the two words this thread owns (orig 2ak4, 2ak4+1)
    const int pA = ((ak4 & 1) << 2) | (ak4 >> 1);   // second word at pA+2

    float acc[4][4][4];
#pragma unroll
    for (int i = 0; i < 4; ++i)
#pragma unroll
        for (int j = 0; j < 4; ++j)
#pragma unroll
            for (int r = 0; r < 4; ++r) acc[i][j][r] = 0.0f;

    float4 ar0, ar1, br0, br1;

    auto load_g = [&](int k0) {
        const float* ap = A + (size_t)(m0 + arow) * lda + k0 + ak4 * 4;
        ar0 = *(const float4*)ap;
        ar1 = *(const float4*)(ap + (size_t)64 * lda);
        if (!TRANSB) {
            const float* bp = B + (size_t)(n0 + arow) * ldb + k0 + ak4 * 4;
            br0 = *(const float4*)bp;
            br1 = *(const float4*)(bp + (size_t)64 * ldb);
        } else {
            const float* bp = B + (size_t)(k0 + bk) * ldb + n0 + bn4 * 4;
            br0 = *(const float4*)bp;
            br1 = *(const float4*)(bp + 64);
        }
    };

    auto store_s = [&](int bu) {
        uint2 hi, lo;
        split4(ar0, hi, lo);
        AsH[bu][arow * 8 + pA] = hi.x;  AsH[bu][arow * 8 + pA + 2] = hi.y;
        AsL[bu][arow * 8 + pA] = lo.x;  AsL[bu][arow * 8 + pA + 2] = lo.y;
        split4(ar1, hi, lo);
        AsH[bu][(arow + 64) * 8 + pA] = hi.x;  AsH[bu][(arow + 64) * 8 + pA + 2] = hi.y;
        AsL[bu][(arow + 64) * 8 + pA] = lo.x;  AsL[bu][(arow + 64) * 8 + pA + 2] = lo.y;
        if (!TRANSB) {
            split4(br0, hi, lo);
            BsH[bu][arow * 8 + pA] = hi.x;  BsH[bu][arow * 8 + pA + 2] = hi.y;
            BsL[bu][arow * 8 + pA] = lo.x;  BsL[bu][arow * 8 + pA + 2] = lo.y;
            split4(br1, hi, lo);
            BsH[bu][(arow + 64) * 8 + pA] = hi.x;  BsH[bu][(arow + 64) * 8 + pA + 2] = hi.y;
            BsL[bu][(arow + 64) * 8 + pA] = lo.x;  BsL[bu][(arow + 64) * 8 + pA + 2] = lo.y;
        } else {
            const int wd = bk >> 1, hf = bk & 1;
            const int pw = (wd < 4) ? (2 * wd) : (2 * (wd - 4) + 1);
            const float* s0 = &br0.x;
            const float* s1 = &br1.x;
#pragma unroll
            for (int j = 0; j < 4; ++j) {
                int r0 = bn4 * 4 + j, r1 = r0 + 64;
                __nv_bfloat16 h = __float2bfloat16(s0[j]);
                __nv_bfloat16 l = __float2bfloat16(s0[j] - __bfloat162float(h));
                ((uint16_t*)&BsH[bu][r0 * 8 + pw])[hf] = __bfloat16_as_ushort(h);
                ((uint16_t*)&BsL[bu][r0 * 8 + pw])[hf] = __bfloat16_as_ushort(l);
                h = __float2bfloat16(s1[j]);
                l = __float2bfloat16(s1[j] - __bfloat162float(h));
                ((uint16_t*)&BsH[bu][r1 * 8 + pw])[hf] = __bfloat16_as_ushort(h);
                ((uint16_t*)&BsL[bu][r1 * 8 + pw])[hf] = __bfloat16_as_ushort(l);
            }
        }
    };

    auto compute = [&](int bu) {
        const int wq = qc * 2;
        uint2 bh[4], bl[4];
#pragma unroll
        for (int nt = 0; nt < 4; ++nt) {
            int rb = (wn * 32 + nt * 8 + qr) * 8 + wq;
            bh[nt] = *(const uint2*)&BsH[bu][rb];
            bl[nt] = *(const uint2*)&BsL[bu][rb];
        }
        {
            uint2 a0[4], a1[4];
#pragma unroll
            for (int mt = 0; mt < 4; ++mt) {
                int ra = (wm * 64 + mt * 16 + qr) * 8 + wq;
                a0[mt] = *(const uint2*)&AsH[bu][ra];
                a1[mt] = *(const uint2*)&AsH[bu][ra + 64];
            }
#pragma unroll
            for (int mt = 0; mt < 4; ++mt)
#pragma unroll
                for (int nt = 0; nt < 4; ++nt) {
                    MMA16(acc[mt][nt], a0[mt].x, a1[mt].x, a0[mt].y, a1[mt].y,
                          bh[nt].x, bh[nt].y);
                    MMA16(acc[mt][nt], a0[mt].x, a1[mt].x, a0[mt].y, a1[mt].y,
                          bl[nt].x, bl[nt].y);
                }
        }
        {
            uint2 a0[4], a1[4];
#pragma unroll
            for (int mt = 0; mt < 4; ++mt) {
                int ra = (wm * 64 + mt * 16 + qr) * 8 + wq;
                a0[mt] = *(const uint2*)&AsL[bu][ra];
                a1[mt] = *(const uint2*)&AsL[bu][ra + 64];
            }
#pragma unroll
            for (int mt = 0; mt < 4; ++mt)
#pragma unroll
                for (int nt = 0; nt < 4; ++nt)
                    MMA16(acc[mt][nt], a0[mt].x, a1[mt].x, a0[mt].y, a1[mt].y,
                          bh[nt].x, bh[nt].y);
        }
    };

    // k32 pipeline: one barrier per 32-k
    const int nkc = K >> 5;
    load_g(0);  store_s(0);
    load_g(16); store_s(1);
    __syncthreads();
    for (int kc = 1; kc < nkc; ++kc) {
        const int st = (kc & 1) * 2;
        const int pv = ((kc - 1) & 1) * 2;
        load_g(kc * 32);
        compute(pv);
        store_s(st);
        load_g(kc * 32 + 16);
        compute(pv + 1);
        store_s(st + 1);
        __syncthreads();
    }
    const int lp = ((nkc - 1) & 1) * 2;
    compute(lp);
    compute(lp + 1);

#pragma unroll
    for (int mt = 0; mt < 4; ++mt) {
#pragma unroll
        for (int nt = 0; nt < 4; ++nt) {
            int row = m0 + wm * 64 + mt * 16 + qr;
            int col = n0 + wn * 32 + nt * 8 + qc * 2;
            float2 v0, v1;
            v0.x = acc[mt][nt][0]; v0.y = acc[mt][nt][1];
            v1.x = acc[mt][nt][2]; v1.y = acc[mt][nt][3];
            if (HASBIAS) {
                v0.x += bias[col]; v0.y += bias[col + 1];
                v1.x += bias[col]; v1.y += bias[col + 1];
            }
            *(float2*)&C[(size_t)row * ldc + col] = v0;
            *(float2*)&C[(size_t)(row + 8) * ldc + col] = v1;
        }
    }
}

// ---------------------------------------------------------------------------
// Fused Q/K/V projection: grid.z selects which of the three GEMMs
__global__ void __launch_bounds__(256, 2)
k_proj3(const float* __restrict__ q, const float* __restrict__ k,
        const float* __restrict__ v,
        const float* __restrict__ Wq, const float* __restrict__ Wk,
        const float* __restrict__ Wv,
        float* __restrict__ Pq, float* __restrict__ Pk, float* __restrict__ Pv)
{
    const float* A; const float* B; float* C;
    if (blockIdx.z == 0)      { A = q; B = Wq; C = Pq; }
    else if (blockIdx.z == 1) { A = k; B = Wk; C = Pk; }
    else                      { A = v; B = Wv; C = Pv; }
    mma_tile<false, false>(A, EE, B, EE, C, HE, EE,
                           blockIdx.y * BM, blockIdx.x * BN, nullptr);
}

__global__ void __launch_bounds__(256, 2)
k_gemm_nt_bias(const float* __restrict__ A, int lda,
               const float* __restrict__ B, int ldb,
               float* __restrict__ C, int ldc, int K,
               const float* __restrict__ bias)
{
    mma_tile<false, true>(A, lda, B, ldb, C, ldc, K,
                          blockIdx.y * BM, blockIdx.x * BN, bias);
}

__global__ void __launch_bounds__(256, 2)
k_energy(const float* __restrict__ Pq, const float* __restrict__ Pk,
         float* __restrict__ Eng)
{
    const int bh = blockIdx.z;
    const int m0 = blockIdx.y * BM;
    const int n0 = blockIdx.x * BN;
    if (n0 > m0) return;
    const float* Q  = Pq + (size_t)bh * SS * EE;
    const float* Kp = Pk + (size_t)bh * SS * EE;
    float* Cc       = Eng + (size_t)bh * SS * SS;
    mma_tile<false, false>(Q, EE, Kp, EE, Cc, SS, EE, m0, n0, nullptr);
}

__global__ void __launch_bounds__(256, 2)
k_pv(const float* __restrict__ P, const float* __restrict__ Pv,
     float* __restrict__ F)
{
    const int bh = blockIdx.z;
    const int b  = bh >> 3;
    const int h  = bh & 7;
    const int m0 = blockIdx.y * BM;
    const int n0 = blockIdx.x * BN;
    const float* Pp = P  + (size_t)bh * SS * SS;
    const float* V  = Pv + (size_t)bh * SS * EE;
    float* Cc = F + (size_t)b * SS * HE + (size_t)h * EE;
    mma_tile<true, false>(Pp, SS, V, EE, Cc, HE, m0 + BM, m0, n0, nullptr);
}

// Causal softmax, in-place, mask-before-scale (scale = 1/8)
__global__ void k_softmax(float* __restrict__ Eng)
{
    const int i = blockIdx.x;
    float* row = Eng + ((size_t)blockIdx.y * SS + i) * SS;
    const int L = i + 1;
    const int tid = threadIdx.x;

    float r[4];
    float lmax = -1e30f;
#pragma unroll
    for (int t = 0; t < 4; ++t) {
        int j = tid + t * 256;
        if (j < L) { r[t] = row[j]; lmax = fmaxf(lmax, r[t]); }
        else         r[t] = -1e30f;
    }
    __shared__ float red[8];
    for (int o = 16; o; o >>= 1) lmax = fmaxf(lmax, __shfl_xor_sync(0xffffffffu, lmax, o));
    if ((tid & 31) == 0) red[tid >> 5] = lmax;
    __syncthreads();
    if (tid == 0) {
        float m = red[0];
#pragma unroll
        for (int w = 1; w < 8; ++w) m = fmaxf(m, red[w]);
        red[0] = m;
    }
    __syncthreads();
    const float m = red[0];
    __syncthreads();

    float lsum = 0.0f;
#pragma unroll
    for (int t = 0; t < 4; ++t) {
        int j = tid + t * 256;
        if (j < L) { r[t] = __expf((r[t] - m) * 0.125f); lsum += r[t]; }
        else         r[t] = 0.0f;
    }
    for (int o = 16; o; o >>= 1) lsum += __shfl_xor_sync(0xffffffffu, lsum, o);
    if ((tid & 31) == 0) red[tid >> 5] = lsum;
    __syncthreads();
    if (tid == 0) {
        float s = red[0];
#pragma unroll
        for (int w = 1; w < 8; ++w) s += red[w];
        red[0] = s;
    }
    __syncthreads();
    const float inv = 1.0f / red[0];
#pragma unroll
    for (int t = 0; t < 4; ++t) {
        int j = tid + t * 256;
        row[j] = r[t] * inv;
    }
}

// ---------------------------------------------------------------------------
extern "C" void kernel_launch(void* const* d_in, const int* in_sizes, int n_in,
                              void* d_out, int out_size)
{
    (void)in_sizes; (void)n_in; (void)out_size;
    const float* k  = (const float*)d_in[0];
    const float* v  = (const float*)d_in[1];
    const float* q  = (const float*)d_in[2];
    const float* Wk = (const float*)d_in[4];
    const float* Wq = (const float*)d_in[5];
    const float* Wv = (const float*)d_in[6];
    const float* Wo = (const float*)d_in[7];
    const float* bo = (const float*)d_in[8];
    float* out = (float*)d_out;

    float *Pq, *Pk, *Pv, *Em, *F;
    cudaGetSymbolAddress((void**)&Pq, g_Pq);
    cudaGetSymbolAddress((void**)&Pk, g_Pk);
    cudaGetSymbolAddress((void**)&Pv, g_Pv);
    cudaGetSymbolAddress((void**)&Em, g_E);
    cudaGetSymbolAddress((void**)&F,  g_F);

    dim3 blk(256);

    // Fused projections: (8192 x 512) @ (4096 x 512)^T x3
    dim3 gp(HE / BN, MQ / BM, 3);
    k_proj3<<<gp, blk>>>(q, k, v, Wq, Wk, Wv, Pq, Pk, Pv);

    // Energy per (b,h), causal skip
    dim3 ge(SS / BN, SS / BM, BB * HH);
    k_energy<<<ge, blk>>>(Pq, Pk, Em);

    k_softmax<<<dim3(SS, BB * HH), 256>>>(Em);

    // P @ V -> F (pre-transposed layout), K trimmed causally
    dim3 gv(EE / BN, SS / BM, BB * HH);
    k_pv<<<gv, blk>>>(Em, Pv, F);

    // Output projection + bias
    dim3 go(EE / BN, MQ / BM);
    k_gemm_nt_bias<<<go, blk>>>(F, HE, Wo, HE, out, EE, HE, bo);
}

// round 14
// speedup vs baseline: 1.2326x; 1.1143x over previous
#include <cuda_runtime.h>
#include <cuda_bf16.h>
#include <cstdint>

#define BB 8
#define SS 1024
#define EE 512
#define HH 8
#define HE 4096
#define MQ 8192

#define BM 128
#define BN 128
#define PAD 20

__device__ float g_Pq[(size_t)MQ * HE];
__device__ float g_Pk[(size_t)MQ * HE];
__device__ float g_Pv[(size_t)MQ * HE];
__device__ float g_E [(size_t)BB * HH * SS * SS];
__device__ float g_F [(size_t)MQ * HE];

__device__ __forceinline__ uint32_t pk2(__nv_bfloat16 a, __nv_bfloat16 b) {
    return ((uint32_t)__bfloat16_as_ushort(b) << 16) | (uint32_t)__bfloat16_as_ushort(a);
}
__device__ __forceinline__ void split4(float4 v, uint2& hi, uint2& lo) {
    __nv_bfloat16 hx = __float2bfloat16(v.x), hy = __float2bfloat16(v.y);
    __nv_bfloat16 hz = __float2bfloat16(v.z), hw = __float2bfloat16(v.w);
    __nv_bfloat16 lx = __float2bfloat16(v.x - __bfloat162float(hx));
    __nv_bfloat16 ly = __float2bfloat16(v.y - __bfloat162float(hy));
    __nv_bfloat16 lz = __float2bfloat16(v.z - __bfloat162float(hz));
    __nv_bfloat16 lw = __float2bfloat16(v.w - __bfloat162float(hw));
    hi.x = pk2(hx, hy); hi.y = pk2(hz, hw);
    lo.x = pk2(lx, ly); lo.y = pk2(lz, lw);
}
__device__ __forceinline__ uint32_t f2tf(float x) {
    uint32_t r;
    asm("cvt.rna.tf32.f32 %0, %1;" : "=r"(r) : "f"(x));
    return r;
}

#define MMA16(acc, a, b) \
    asm volatile("mma.sync.aligned.m16n8k16.row.col.f32.bf16.bf16.f32 " \
        "{%0,%1,%2,%3},{%4,%5,%6,%7},{%8,%9},{%0,%1,%2,%3};" \
        : "+f"((acc)[0]), "+f"((acc)[1]), "+f"((acc)[2]), "+f"((acc)[3]) \
        : "r"((a)[0]), "r"((a)[1]), "r"((a)[2]), "r"((a)[3]), \
          "r"((b)[0]), "r"((b)[1]))

// ===========================================================================
// bf16x3 tile (R8-proven, NT only): C = A @ B^T
// ===========================================================================
__device__ __forceinline__ void mma_bf3(
    const float* __restrict__ A, int lda,
    const float* __restrict__ B, int ldb,
    float* __restrict__ C, int ldc,
    int K, int m0, int n0)
{
    __shared__ uint32_t AsH[4][BM * 8], AsL[4][BM * 8];
    __shared__ uint32_t BsH[4][BN * 8], BsL[4][BN * 8];

    const int tid  = threadIdx.x;
    const int wid  = tid >> 5;
    const int lane = tid & 31;
    const int wm   = wid & 1;
    const int wn   = wid >> 1;
    const int qr   = lane >> 2;
    const int qc   = lane & 3;
    const int swz  = qr & 4;

    const int arow = tid >> 2;
    const int ak4  = tid & 3;

    float acc[4][4][4];
#pragma unroll
    for (int i = 0; i < 4; ++i)
#pragma unroll
        for (int j = 0; j < 4; ++j)
#pragma unroll
            for (int r = 0; r < 4; ++r) acc[i][j][r] = 0.0f;

    float4 ar0, ar1, br0, br1;

    auto load_g = [&](int k0) {
        const float* ap = A + (size_t)(m0 + arow) * lda + k0 + ak4 * 4;
        ar0 = *(const float4*)ap;
        ar1 = *(const float4*)(ap + (size_t)64 * lda);
        const float* bp = B + (size_t)(n0 + arow) * ldb + k0 + ak4 * 4;
        br0 = *(const float4*)bp;
        br1 = *(const float4*)(bp + (size_t)64 * ldb);
    };

    auto store_s = [&](int bu) {
        uint2 hi, lo;
        const int w0  = (ak4 * 2) ^ ((arow & 4) ? 4 : 0);
        const int w0b = (ak4 * 2) ^ (((arow + 64) & 4) ? 4 : 0);
        split4(ar0, hi, lo);
        *(uint2*)&AsH[bu][arow * 8 + w0] = hi;
        *(uint2*)&AsL[bu][arow * 8 + w0] = lo;
        split4(ar1, hi, lo);
        *(uint2*)&AsH[bu][(arow + 64) * 8 + w0b] = hi;
        *(uint2*)&AsL[bu][(arow + 64) * 8 + w0b] = lo;
        split4(br0, hi, lo);
        *(uint2*)&BsH[bu][arow * 8 + w0] = hi;
        *(uint2*)&BsL[bu][arow * 8 + w0] = lo;
        split4(br1, hi, lo);
        *(uint2*)&BsH[bu][(arow + 64) * 8 + w0b] = hi;
        *(uint2*)&BsL[bu][(arow + 64) * 8 + w0b] = lo;
    };

    auto compute = [&](int bu) {
        const int wA = qc ^ swz, wA2 = (qc + 4) ^ swz;
        uint32_t bh[4][2], bl[4][2];
#pragma unroll
        for (int nt = 0; nt < 4; ++nt) {
            int rb = (wn * 32 + nt * 8 + qr) * 8;
            bh[nt][0] = BsH[bu][rb + wA];  bh[nt][1] = BsH[bu][rb + wA2];
            bl[nt][0] = BsL[bu][rb + wA];  bl[nt][1] = BsL[bu][rb + wA2];
        }
        {
            uint32_t a[4][4];
#pragma unroll
            for (int mt = 0; mt < 4; ++mt) {
                int ra = (wm * 64 + mt * 16 + qr) * 8;
                a[mt][0] = AsH[bu][ra + wA];   a[mt][1] = AsH[bu][ra + 64 + wA];
                a[mt][2] = AsH[bu][ra + wA2];  a[mt][3] = AsH[bu][ra + 64 + wA2];
            }
#pragma unroll
            for (int mt = 0; mt < 4; ++mt)
#pragma unroll
                for (int nt = 0; nt < 4; ++nt) {
                    MMA16(acc[mt][nt], a[mt], bh[nt]);
                    MMA16(acc[mt][nt], a[mt], bl[nt]);
                }
        }
        {
            uint32_t a[4][4];
#pragma unroll
            for (int mt = 0; mt < 4; ++mt) {
                int ra = (wm * 64 + mt * 16 + qr) * 8;
                a[mt][0] = AsL[bu][ra + wA];   a[mt][1] = AsL[bu][ra + 64 + wA];
                a[mt][2] = AsL[bu][ra + wA2];  a[mt][3] = AsL[bu][ra + 64 + wA2];
            }
#pragma unroll
            for (int mt = 0; mt < 4; ++mt)
#pragma unroll
                for (int nt = 0; nt < 4; ++nt)
                    MMA16(acc[mt][nt], a[mt], bh[nt]);
        }
    };

    const int nkc = K >> 5;
    load_g(0);  store_s(0);
    load_g(16); store_s(1);
    __syncthreads();
    for (int kc = 1; kc < nkc; ++kc) {
        const int st = (kc & 1) * 2;
        const int pv = ((kc - 1) & 1) * 2;
        load_g(kc * 32);
        compute(pv);
        store_s(st);
        load_g(kc * 32 + 16);
        compute(pv + 1);
        store_s(st + 1);
        __syncthreads();
    }
    const int lp = ((nkc - 1) & 1) * 2;
    compute(lp);
    compute(lp + 1);

#pragma unroll
    for (int mt = 0; mt < 4; ++mt)
#pragma unroll
        for (int nt = 0; nt < 4; ++nt) {
            int row = m0 + wm * 64 + mt * 16 + qr;
            int col = n0 + wn * 32 + nt * 8 + qc * 2;
            float2 v0, v1;
            v0.x = acc[mt][nt][0]; v0.y = acc[mt][nt][1];
            v1.x = acc[mt][nt][2]; v1.y = acc[mt][nt][3];
            *(float2*)&C[(size_t)row * ldc + col] = v0;
            *(float2*)&C[(size_t)(row + 8) * ldc + col] = v1;
        }
}

// ===========================================================================
// tf32 single-pass tile (R3-proven numerics): C = A @ op(B)
// ===========================================================================
template<bool TRANSB, bool HASBIAS>
__device__ __forceinline__ void mma_tf32(
    const float* __restrict__ A, int lda,
    const float* __restrict__ B, int ldb,
    float* __restrict__ C, int ldc,
    int K, int m0, int n0, const float* __restrict__ bias)
{
    __shared__ uint32_t As[2][BM * PAD];
    __shared__ uint32_t Bs[2][BN * PAD];

    const int tid  = threadIdx.x;
    const int wid  = tid >> 5;
    const int lane = tid & 31;
    const int wm   = wid & 1;
    const int wn   = wid >> 1;
    const int qr   = lane >> 2;
    const int qc   = lane & 3;

    const int arow = tid >> 2;
    const int ak4  = tid & 3;
    const int bk   = tid & 15;
    const int bn4  = tid >> 4;

    float acc[4][4][4];
#pragma unroll
    for (int i = 0; i < 4; ++i)
#pragma unroll
        for (int j = 0; j < 4; ++j)
#pragma unroll
            for (int r = 0; r < 4; ++r) acc[i][j][r] = 0.0f;

    float4 ar0, ar1, br0, br1;

    auto load_g = [&](int k0) {
        const float* ap = A + (size_t)(m0 + arow) * lda + k0 + ak4 * 4;
        ar0 = *(const float4*)ap;
        ar1 = *(const float4*)(ap + (size_t)64 * lda);
        if (!TRANSB) {
            const float* bp = B + (size_t)(n0 + arow) * ldb + k0 + ak4 * 4;
            br0 = *(const float4*)bp;
            br1 = *(const float4*)(bp + (size_t)64 * ldb);
        } else {
            const float* bp = B + (size_t)(k0 + bk) * ldb + n0 + bn4 * 4;
            br0 = *(const float4*)bp;
            br1 = *(const float4*)(bp + 64);
        }
    };

    auto store_s = [&](int st) {
        uint32_t* as = As[st];
        uint32_t* bs = Bs[st];
        {
            uint4 v;
            v.x = f2tf(ar0.x); v.y = f2tf(ar0.y); v.z = f2tf(ar0.z); v.w = f2tf(ar0.w);
            *(uint4*)&as[arow * PAD + ak4 * 4] = v;
            v.x = f2tf(ar1.x); v.y = f2tf(ar1.y); v.z = f2tf(ar1.z); v.w = f2tf(ar1.w);
            *(uint4*)&as[(arow + 64) * PAD + ak4 * 4] = v;
        }
        if (!TRANSB) {
            uint4 v;
            v.x = f2tf(br0.x); v.y = f2tf(br0.y); v.z = f2tf(br0.z); v.w = f2tf(br0.w);
            *(uint4*)&bs[arow * PAD + ak4 * 4] = v;
            v.x = f2tf(br1.x); v.y = f2tf(br1.y); v.z = f2tf(br1.z); v.w = f2tf(br1.w);
            *(uint4*)&bs[(arow + 64) * PAD + ak4 * 4] = v;
        } else {
            bs[(bn4 * 4 + 0) * PAD + bk] = f2tf(br0.x);
            bs[(bn4 * 4 + 1) * PAD + bk] = f2tf(br0.y);
            bs[(bn4 * 4 + 2) * PAD + bk] = f2tf(br0.z);
            bs[(bn4 * 4 + 3) * PAD + bk] = f2tf(br0.w);
            bs[((bn4 + 16) * 4 + 0) * PAD + bk] = f2tf(br1.x);
            bs[((bn4 + 16) * 4 + 1) * PAD + bk] = f2tf(br1.y);
            bs[((bn4 + 16) * 4 + 2) * PAD + bk] = f2tf(br1.z);
            bs[((bn4 + 16) * 4 + 3) * PAD + bk] = f2tf(br1.w);
        }
    };

    auto compute = [&](int st) {
        const uint32_t* as = As[st];
        const uint32_t* bs = Bs[st];
#pragma unroll
        for (int s = 0; s < 2; ++s) {
            uint32_t af[4][4], bf[4][2];
#pragma unroll
            for (int mt = 0; mt < 4; ++mt) {
                int base = (wm * 64 + mt * 16 + qr) * PAD + s * 8 + qc;
                af[mt][0] = as[base];
                af[mt][1] = as[base + 8 * PAD];
                af[mt][2] = as[base + 4];
                af[mt][3] = as[base + 8 * PAD + 4];
            }
#pragma unroll
            for (int nt = 0; nt < 4; ++nt) {
                int base = (wn * 32 + nt * 8 + qr) * PAD + s * 8 + qc;
                bf[nt][0] = bs[base];
                bf[nt][1] = bs[base + 4];
            }
#pragma unroll
            for (int mt = 0; mt < 4; ++mt)
#pragma unroll
                for (int nt = 0; nt < 4; ++nt)
                    asm volatile(
                        "mma.sync.aligned.m16n8k8.row.col.f32.tf32.tf32.f32 "
                        "{%0,%1,%2,%3}, {%4,%5,%6,%7}, {%8,%9}, {%0,%1,%2,%3};\n"
                        : "+f"(acc[mt][nt][0]), "+f"(acc[mt][nt][1]),
                          "+f"(acc[mt][nt][2]), "+f"(acc[mt][nt][3])
                        : "r"(af[mt][0]), "r"(af[mt][1]),
                          "r"(af[mt][2]), "r"(af[mt][3]),
                          "r"(bf[nt][0]), "r"(bf[nt][1]));
        }
    };

    const int niter = K >> 4;
    load_g(0);
    store_s(0);
    __syncthreads();
    for (int kt = 1; kt < niter; ++kt) {
        load_g(kt * 16);
        compute((kt - 1) & 1);
        store_s(kt & 1);
        __syncthreads();
    }
    compute((niter - 1) & 1);

#pragma unroll
    for (int mt = 0; mt < 4; ++mt)
#pragma unroll
        for (int nt = 0; nt < 4; ++nt) {
            int row = m0 + wm * 64 + mt * 16 + qr;
            int col = n0 + wn * 32 + nt * 8 + qc * 2;
            float2 v0, v1;
            v0.x = acc[mt][nt][0]; v0.y = acc[mt][nt][1];
            v1.x = acc[mt][nt][2]; v1.y = acc[mt][nt][3];
            if (HASBIAS) {
                v0.x += bias[col]; v0.y += bias[col + 1];
                v1.x += bias[col]; v1.y += bias[col + 1];
            }
            *(float2*)&C[(size_t)row * ldc + col] = v0;
            *(float2*)&C[(size_t)(row + 8) * ldc + col] = v1;
        }
}

// ---------------------------------------------------------------------------
// Kernels
// ---------------------------------------------------------------------------
__global__ void __launch_bounds__(256, 2)
k_proj3(const float* __restrict__ q, const float* __restrict__ k,
        const float* __restrict__ v,
        const float* __restrict__ Wq, const float* __restrict__ Wk,
        const float* __restrict__ Wv,
        float* __restrict__ Pq, float* __restrict__ Pk, float* __restrict__ Pv)
{
    const float* A; const float* B; float* C;
    if (blockIdx.z == 0)      { A = q; B = Wq; C = Pq; }
    else if (blockIdx.z == 1) { A = k; B = Wk; C = Pk; }
    else                      { A = v; B = Wv; C = Pv; }
    mma_bf3(A, EE, B, EE, C, HE, EE, blockIdx.y * BM, blockIdx.x * BN);
}

__global__ void __launch_bounds__(256, 2)
k_energy(const float* __restrict__ Pq, const float* __restrict__ Pk,
         float* __restrict__ Eng)
{
    const int bh = blockIdx.z;
    const int m0 = blockIdx.y * BM;
    const int n0 = blockIdx.x * BN;
    if (n0 > m0) return;
    mma_bf3(Pq + (size_t)bh * SS * EE, EE,
            Pk + (size_t)bh * SS * EE, EE,
            Eng + (size_t)bh * SS * SS, SS, EE, m0, n0);
}

__global__ void __launch_bounds__(256, 2)
k_pv(const float* __restrict__ P, const float* __restrict__ Pv,
     float* __restrict__ F)
{
    const int bh = blockIdx.z;
    const int b  = bh >> 3;
    const int h  = bh & 7;
    const int m0 = blockIdx.y * BM;
    const int n0 = blockIdx.x * BN;
    mma_tf32<true, false>(P + (size_t)bh * SS * SS, SS,
                          Pv + (size_t)bh * SS * EE, EE,
                          F + (size_t)b * SS * HE + (size_t)h * EE, HE,
                          m0 + BM, m0, n0, nullptr);
}

__global__ void __launch_bounds__(256, 2)
k_outp(const float* __restrict__ F, const float* __restrict__ Wo,
       float* __restrict__ C, const float* __restrict__ bias)
{
    mma_tf32<false, true>(F, HE, Wo, HE, C, EE, HE,
                          blockIdx.y * BM, blockIdx.x * BN, bias);
}

// Causal softmax, in-place, mask-before-scale (scale = 1/8)
__global__ void k_softmax(float* __restrict__ Eng)
{
    const int i = blockIdx.x;
    float* row = Eng + ((size_t)blockIdx.y * SS + i) * SS;
    const int L = i + 1;
    const int tid = threadIdx.x;

    float r[4];
    float lmax = -1e30f;
#pragma unroll
    for (int t = 0; t < 4; ++t) {
        int j = tid + t * 256;
        if (j < L) { r[t] = row[j]; lmax = fmaxf(lmax, r[t]); }
        else         r[t] = -1e30f;
    }
    __shared__ float red[8];
    for (int o = 16; o; o >>= 1) lmax = fmaxf(lmax, __shfl_xor_sync(0xffffffffu, lmax, o));
    if ((tid & 31) == 0) red[tid >> 5] = lmax;
    __syncthreads();
    if (tid == 0) {
        float m = red[0];
#pragma unroll
        for (int w = 1; w < 8; ++w) m = fmaxf(m, red[w]);
        red[0] = m;
    }
    __syncthreads();
    const float m = red[0];
    __syncthreads();

    float lsum = 0.0f;
#pragma unroll
    for (int t = 0; t < 4; ++t) {
        int j = tid + t * 256;
        if (j < L) { r[t] = __expf((r[t] - m) * 0.125f); lsum += r[t]; }
        else         r[t] = 0.0f;
    }
    for (int o = 16; o; o >>= 1) lsum += __shfl_xor_sync(0xffffffffu, lsum, o);
    if ((tid & 31) == 0) red[tid >> 5] = lsum;
    __syncthreads();
    if (tid == 0) {
        float s = red[0];
#pragma unroll
        for (int w = 1; w < 8; ++w) s += red[w];
        red[0] = s;
    }
    __syncthreads();
    const float inv = 1.0f / red[0];
#pragma unroll
    for (int t = 0; t < 4; ++t) {
        int j = tid + t * 256;
        row[j] = r[t] * inv;
    }
}

// ---------------------------------------------------------------------------
extern "C" void kernel_launch(void* const* d_in, const int* in_sizes, int n_in,
                              void* d_out, int out_size)
{
    (void)in_sizes; (void)n_in; (void)out_size;
    const float* k  = (const float*)d_in[0];
    const float* v  = (const float*)d_in[1];
    const float* q  = (const float*)d_in[2];
    const float* Wk = (const float*)d_in[4];
    const float* Wq = (const float*)d_in[5];
    const float* Wv = (const float*)d_in[6];
    const float* Wo = (const float*)d_in[7];
    const float* bo = (const float*)d_in[8];
    float* out = (float*)d_out;

    float *Pq, *Pk, *Pv, *Em, *F;
    cudaGetSymbolAddress((void**)&Pq, g_Pq);
    cudaGetSymbolAddress((void**)&Pk, g_Pk);
    cudaGetSymbolAddress((void**)&Pv, g_Pv);
    cudaGetSymbolAddress((void**)&Em, g_E);
    cudaGetSymbolAddress((void**)&F,  g_F);

    dim3 blk(256);

    // Fused projections (bf16x3)
    dim3 gp(HE / BN, MQ / BM, 3);
    k_proj3<<<gp, blk>>>(q, k, v, Wq, Wk, Wv, Pq, Pk, Pv);

    // Energy per (b,h), causal skip (bf16x3)
    dim3 ge(SS / BN, SS / BM, BB * HH);
    k_energy<<<ge, blk>>>(Pq, Pk, Em);

    k_softmax<<<dim3(SS, BB * HH), 256>>>(Em);

    // P @ V (tf32, K trimmed causally)
    dim3 gv(EE / BN, SS / BM, BB * HH);
    k_pv<<<gv, blk>>>(Em, Pv, F);

    // Output projection + bias (tf32)
    dim3 go(EE / BN, MQ / BM);
    k_outp<<<go, blk>>>(F, Wo, out, bo);
}

// round 15
// speedup vs baseline: 1.2747x; 1.0342x over previous
#include <cuda_runtime.h>
#include <cuda_bf16.h>
#include <cstdint>

#define BB 8
#define SS 1024
#define EE 512
#define HH 8
#define HE 4096
#define MQ 8192

#define BM 128
#define BN 128
#define PAD 20

__device__ float g_Pq [(size_t)MQ * HE];
__device__ float g_Pk [(size_t)MQ * HE];
__device__ float g_Pv [(size_t)MQ * HE];
__device__ float g_PvT[(size_t)MQ * HE];      // [bh][e][s]
__device__ float g_E  [(size_t)BB * HH * SS * SS];
__device__ float g_F  [(size_t)MQ * HE];

__device__ __forceinline__ uint32_t pk2(__nv_bfloat16 a, __nv_bfloat16 b) {
    return ((uint32_t)__bfloat16_as_ushort(b) << 16) | (uint32_t)__bfloat16_as_ushort(a);
}
__device__ __forceinline__ void split4(float4 v, uint2& hi, uint2& lo) {
    __nv_bfloat16 hx = __float2bfloat16(v.x), hy = __float2bfloat16(v.y);
    __nv_bfloat16 hz = __float2bfloat16(v.z), hw = __float2bfloat16(v.w);
    __nv_bfloat16 lx = __float2bfloat16(v.x - __bfloat162float(hx));
    __nv_bfloat16 ly = __float2bfloat16(v.y - __bfloat162float(hy));
    __nv_bfloat16 lz = __float2bfloat16(v.z - __bfloat162float(hz));
    __nv_bfloat16 lw = __float2bfloat16(v.w - __bfloat162float(hw));
    hi.x = pk2(hx, hy); hi.y = pk2(hz, hw);
    lo.x = pk2(lx, ly); lo.y = pk2(lz, lw);
}
__device__ __forceinline__ uint32_t f2tf(float x) {
    uint32_t r;
    asm("cvt.rna.tf32.f32 %0, %1;" : "=r"(r) : "f"(x));
    return r;
}

#define MMA16(acc, a, b) \
    asm volatile("mma.sync.aligned.m16n8k16.row.col.f32.bf16.bf16.f32 " \
        "{%0,%1,%2,%3},{%4,%5,%6,%7},{%8,%9},{%0,%1,%2,%3};" \
        : "+f"((acc)[0]), "+f"((acc)[1]), "+f"((acc)[2]), "+f"((acc)[3]) \
        : "r"((a)[0]), "r"((a)[1]), "r"((a)[2]), "r"((a)[3]), \
          "r"((b)[0]), "r"((b)[1]))

// ===========================================================================
// bf16x3 tile (R8-proven, NT only): C = A @ B^T
// ===========================================================================
__device__ __forceinline__ void mma_bf3(
    const float* __restrict__ A, int lda,
    const float* __restrict__ B, int ldb,
    float* __restrict__ C, int ldc,
    int K, int m0, int n0)
{
    __shared__ uint32_t AsH[4][BM * 8], AsL[4][BM * 8];
    __shared__ uint32_t BsH[4][BN * 8], BsL[4][BN * 8];

    const int tid  = threadIdx.x;
    const int wid  = tid >> 5;
    const int lane = tid & 31;
    const int wm   = wid & 1;
    const int wn   = wid >> 1;
    const int qr   = lane >> 2;
    const int qc   = lane & 3;
    const int swz  = qr & 4;

    const int arow = tid >> 2;
    const int ak4  = tid & 3;

    float acc[4][4][4];
#pragma unroll
    for (int i = 0; i < 4; ++i)
#pragma unroll
        for (int j = 0; j < 4; ++j)
#pragma unroll
            for (int r = 0; r < 4; ++r) acc[i][j][r] = 0.0f;

    float4 ar0, ar1, br0, br1;

    auto load_g = [&](int k0) {
        const float* ap = A + (size_t)(m0 + arow) * lda + k0 + ak4 * 4;
        ar0 = *(const float4*)ap;
        ar1 = *(const float4*)(ap + (size_t)64 * lda);
        const float* bp = B + (size_t)(n0 + arow) * ldb + k0 + ak4 * 4;
        br0 = *(const float4*)bp;
        br1 = *(const float4*)(bp + (size_t)64 * ldb);
    };

    auto store_s = [&](int bu) {
        uint2 hi, lo;
        const int w0  = (ak4 * 2) ^ ((arow & 4) ? 4 : 0);
        const int w0b = (ak4 * 2) ^ (((arow + 64) & 4) ? 4 : 0);
        split4(ar0, hi, lo);
        *(uint2*)&AsH[bu][arow * 8 + w0] = hi;
        *(uint2*)&AsL[bu][arow * 8 + w0] = lo;
        split4(ar1, hi, lo);
        *(uint2*)&AsH[bu][(arow + 64) * 8 + w0b] = hi;
        *(uint2*)&AsL[bu][(arow + 64) * 8 + w0b] = lo;
        split4(br0, hi, lo);
        *(uint2*)&BsH[bu][arow * 8 + w0] = hi;
        *(uint2*)&BsL[bu][arow * 8 + w0] = lo;
        split4(br1, hi, lo);
        *(uint2*)&BsH[bu][(arow + 64) * 8 + w0b] = hi;
        *(uint2*)&BsL[bu][(arow + 64) * 8 + w0b] = lo;
    };

    auto compute = [&](int bu) {
        const int wA = qc ^ swz, wA2 = (qc + 4) ^ swz;
        uint32_t bh[4][2], bl[4][2];
#pragma unroll
        for (int nt = 0; nt < 4; ++nt) {
            int rb = (wn * 32 + nt * 8 + qr) * 8;
            bh[nt][0] = BsH[bu][rb + wA];  bh[nt][1] = BsH[bu][rb + wA2];
            bl[nt][0] = BsL[bu][rb + wA];  bl[nt][1] = BsL[bu][rb + wA2];
        }
        {
            uint32_t a[4][4];
#pragma unroll
            for (int mt = 0; mt < 4; ++mt) {
                int ra = (wm * 64 + mt * 16 + qr) * 8;
                a[mt][0] = AsH[bu][ra + wA];   a[mt][1] = AsH[bu][ra + 64 + wA];
                a[mt][2] = AsH[bu][ra + wA2];  a[mt][3] = AsH[bu][ra + 64 + wA2];
            }
#pragma unroll
            for (int mt = 0; mt < 4; ++mt)
#pragma unroll
                for (int nt = 0; nt < 4; ++nt) {
                    MMA16(acc[mt][nt], a[mt], bh[nt]);
                    MMA16(acc[mt][nt], a[mt], bl[nt]);
                }
        }
        {
            uint32_t a[4][4];
#pragma unroll
            for (int mt = 0; mt < 4; ++mt) {
                int ra = (wm * 64 + mt * 16 + qr) * 8;
                a[mt][0] = AsL[bu][ra + wA];   a[mt][1] = AsL[bu][ra + 64 + wA];
                a[mt][2] = AsL[bu][ra + wA2];  a[mt][3] = AsL[bu][ra + 64 + wA2];
            }
#pragma unroll
            for (int mt = 0; mt < 4; ++mt)
#pragma unroll
                for (int nt = 0; nt < 4; ++nt)
                    MMA16(acc[mt][nt], a[mt], bh[nt]);
        }
    };

    const int nkc = K >> 5;
    load_g(0);  store_s(0);
    load_g(16); store_s(1);
    __syncthreads();
    for (int kc = 1; kc < nkc; ++kc) {
        const int st = (kc & 1) * 2;
        const int pv = ((kc - 1) & 1) * 2;
        load_g(kc * 32);
        compute(pv);
        store_s(st);
        load_g(kc * 32 + 16);
        compute(pv + 1);
        store_s(st + 1);
        __syncthreads();
    }
    const int lp = ((nkc - 1) & 1) * 2;
    compute(lp);
    compute(lp + 1);

#pragma unroll
    for (int mt = 0; mt < 4; ++mt)
#pragma unroll
        for (int nt = 0; nt < 4; ++nt) {
            int row = m0 + wm * 64 + mt * 16 + qr;
            int col = n0 + wn * 32 + nt * 8 + qc * 2;
            float2 v0, v1;
            v0.x = acc[mt][nt][0]; v0.y = acc[mt][nt][1];
            v1.x = acc[mt][nt][2]; v1.y = acc[mt][nt][3];
            *(float2*)&C[(size_t)row * ldc + col] = v0;
            *(float2*)&C[(size_t)(row + 8) * ldc + col] = v1;
        }
}

// ===========================================================================
// tf32 single-pass tile (NT): C = A @ B^T
// ===========================================================================
template<bool HASBIAS>
__device__ __forceinline__ void mma_tf32(
    const float* __restrict__ A, int lda,
    const float* __restrict__ B, int ldb,
    float* __restrict__ C, int ldc,
    int K, int m0, int n0, const float* __restrict__ bias)
{
    __shared__ uint32_t As[2][BM * PAD];
    __shared__ uint32_t Bs[2][BN * PAD];

    const int tid  = threadIdx.x;
    const int wid  = tid >> 5;
    const int lane = tid & 31;
    const int wm   = wid & 1;
    const int wn   = wid >> 1;
    const int qr   = lane >> 2;
    const int qc   = lane & 3;

    const int arow = tid >> 2;
    const int ak4  = tid & 3;

    float acc[4][4][4];
#pragma unroll
    for (int i = 0; i < 4; ++i)
#pragma unroll
        for (int j = 0; j < 4; ++j)
#pragma unroll
            for (int r = 0; r < 4; ++r) acc[i][j][r] = 0.0f;

    float4 ar0, ar1, br0, br1;

    auto load_g = [&](int k0) {
        const float* ap = A + (size_t)(m0 + arow) * lda + k0 + ak4 * 4;
        ar0 = *(const float4*)ap;
        ar1 = *(const float4*)(ap + (size_t)64 * lda);
        const float* bp = B + (size_t)(n0 + arow) * ldb + k0 + ak4 * 4;
        br0 = *(const float4*)bp;
        br1 = *(const float4*)(bp + (size_t)64 * ldb);
    };

    auto store_s = [&](int st) {
        uint32_t* as = As[st];
        uint32_t* bs = Bs[st];
        uint4 v;
        v.x = f2tf(ar0.x); v.y = f2tf(ar0.y); v.z = f2tf(ar0.z); v.w = f2tf(ar0.w);
        *(uint4*)&as[arow * PAD + ak4 * 4] = v;
        v.x = f2tf(ar1.x); v.y = f2tf(ar1.y); v.z = f2tf(ar1.z); v.w = f2tf(ar1.w);
        *(uint4*)&as[(arow + 64) * PAD + ak4 * 4] = v;
        v.x = f2tf(br0.x); v.y = f2tf(br0.y); v.z = f2tf(br0.z); v.w = f2tf(br0.w);
        *(uint4*)&bs[arow * PAD + ak4 * 4] = v;
        v.x = f2tf(br1.x); v.y = f2tf(br1.y); v.z = f2tf(br1.z); v.w = f2tf(br1.w);
        *(uint4*)&bs[(arow + 64) * PAD + ak4 * 4] = v;
    };

    auto compute = [&](int st) {
        const uint32_t* as = As[st];
        const uint32_t* bs = Bs[st];
#pragma unroll
        for (int s = 0; s < 2; ++s) {
            uint32_t af[4][4], bf[4][2];
#pragma unroll
            for (int mt = 0; mt < 4; ++mt) {
                int base = (wm * 64 + mt * 16 + qr) * PAD + s * 8 + qc;
                af[mt][0] = as[base];
                af[mt][1] = as[base + 8 * PAD];
                af[mt][2] = as[base + 4];
                af[mt][3] = as[base + 8 * PAD + 4];
            }
#pragma unroll
            for (int nt = 0; nt < 4; ++nt) {
                int base = (wn * 32 + nt * 8 + qr) * PAD + s * 8 + qc;
                bf[nt][0] = bs[base];
                bf[nt][1] = bs[base + 4];
            }
#pragma unroll
            for (int mt = 0; mt < 4; ++mt)
#pragma unroll
                for (int nt = 0; nt < 4; ++nt)
                    asm volatile(
                        "mma.sync.aligned.m16n8k8.row.col.f32.tf32.tf32.f32 "
                        "{%0,%1,%2,%3}, {%4,%5,%6,%7}, {%8,%9}, {%0,%1,%2,%3};\n"
                        : "+f"(acc[mt][nt][0]), "+f"(acc[mt][nt][1]),
                          "+f"(acc[mt][nt][2]), "+f"(acc[mt][nt][3])
                        : "r"(af[mt][0]), "r"(af[mt][1]),
                          "r"(af[mt][2]), "r"(af[mt][3]),
                          "r"(bf[nt][0]), "r"(bf[nt][1]));
        }
    };

    const int niter = K >> 4;
    load_g(0);
    store_s(0);
    __syncthreads();
    for (int kt = 1; kt < niter; ++kt) {
        load_g(kt * 16);
        compute((kt - 1) & 1);
        store_s(kt & 1);
        __syncthreads();
    }
    compute((niter - 1) & 1);

#pragma unroll
    for (int mt = 0; mt < 4; ++mt)
#pragma unroll
        for (int nt = 0; nt < 4; ++nt) {
            int row = m0 + wm * 64 + mt * 16 + qr;
            int col = n0 + wn * 32 + nt * 8 + qc * 2;
            float2 v0, v1;
            v0.x = acc[mt][nt][0]; v0.y = acc[mt][nt][1];
            v1.x = acc[mt][nt][2]; v1.y = acc[mt][nt][3];
            if (HASBIAS) {
                v0.x += bias[col]; v0.y += bias[col + 1];
                v1.x += bias[col]; v1.y += bias[col + 1];
            }
            *(float2*)&C[(size_t)row * ldc + col] = v0;
            *(float2*)&C[(size_t)(row + 8) * ldc + col] = v1;
        }
}

// ---------------------------------------------------------------------------
// Kernels
// ---------------------------------------------------------------------------
__global__ void __launch_bounds__(256, 2)
k_proj3(const float* __restrict__ q, const float* __restrict__ k,
        const float* __restrict__ v,
        const float* __restrict__ Wq, const float* __restrict__ Wk,
        const float* __restrict__ Wv,
        float* __restrict__ Pq, float* __restrict__ Pk, float* __restrict__ Pv)
{
    const float* A; const float* B; float* C;
    if (blockIdx.z == 0)      { A = q; B = Wq; C = Pq; }
    else if (blockIdx.z == 1) { A = k; B = Wk; C = Pk; }
    else                      { A = v; B = Wv; C = Pv; }
    mma_bf3(A, EE, B, EE, C, HE, EE, blockIdx.y * BM, blockIdx.x * BN);
}

// Transpose Pv [bh][s][e] -> PvT [bh][e][s], 32x32 tiles
__global__ void __launch_bounds__(256)
k_transp(const float* __restrict__ Pv, float* __restrict__ PvT)
{
    __shared__ float t[32][33];
    const int bh = blockIdx.z;
    const int s0 = blockIdx.x * 32;
    const int e0 = blockIdx.y * 32;
    const int tx = threadIdx.x & 31;
    const int ty = threadIdx.x >> 5;     // 0..7
    const float* src = Pv  + (size_t)bh * SS * EE;
    float*       dst = PvT + (size_t)bh * EE * SS;
#pragma unroll
    for (int i = 0; i < 4; ++i)
        t[ty + i * 8][tx] = src[(size_t)(s0 + ty + i * 8) * EE + e0 + tx];
    __syncthreads();
#pragma unroll
    for (int i = 0; i < 4; ++i)
        dst[(size_t)(e0 + ty + i * 8) * SS + s0 + tx] = t[tx][ty + i * 8];
}

__global__ void __launch_bounds__(256, 2)
k_energy(const float* __restrict__ Pq, const float* __restrict__ Pk,
         float* __restrict__ Eng)
{
    const int bh = blockIdx.z;
    const int m0 = blockIdx.y * BM;
    const int n0 = blockIdx.x * BN;
    if (n0 > m0) return;
    mma_bf3(Pq + (size_t)bh * SS * EE, EE,
            Pk + (size_t)bh * SS * EE, EE,
            Eng + (size_t)bh * SS * SS, SS, EE, m0, n0);
}

__global__ void __launch_bounds__(256, 2)
k_pv(const float* __restrict__ P, const float* __restrict__ PvT,
     float* __restrict__ F)
{
    const int bh = blockIdx.z;
    const int b  = bh >> 3;
    const int h  = bh & 7;
    const int m0 = blockIdx.y * BM;
    const int n0 = blockIdx.x * BN;
    mma_tf32<false>(P + (size_t)bh * SS * SS, SS,
                    PvT + (size_t)bh * EE * SS, SS,
                    F + (size_t)b * SS * HE + (size_t)h * EE, HE,
                    m0 + BM, m0, n0, nullptr);
}

__global__ void __launch_bounds__(256, 2)
k_outp(const float* __restrict__ F, const float* __restrict__ Wo,
       float* __restrict__ C, const float* __restrict__ bias)
{
    mma_tf32<true>(F, HE, Wo, HE, C, EE, HE,
                   blockIdx.y * BM, blockIdx.x * BN, bias);
}

// Causal softmax, in-place, mask-before-scale (scale = 1/8)
__global__ void k_softmax(float* __restrict__ Eng)
{
    const int i = blockIdx.x;
    float* row = Eng + ((size_t)blockIdx.y * SS + i) * SS;
    const int L = i + 1;
    const int tid = threadIdx.x;

    float r[4];
    float lmax = -1e30f;
#pragma unroll
    for (int t = 0; t < 4; ++t) {
        int j = tid + t * 256;
        if (j < L) { r[t] = row[j]; lmax = fmaxf(lmax, r[t]); }
        else         r[t] = -1e30f;
    }
    __shared__ float red[8];
    for (int o = 16; o; o >>= 1) lmax = fmaxf(lmax, __shfl_xor_sync(0xffffffffu, lmax, o));
    if ((tid & 31) == 0) red[tid >> 5] = lmax;
    __syncthreads();
    if (tid == 0) {
        float m = red[0];
#pragma unroll
        for (int w = 1; w < 8; ++w) m = fmaxf(m, red[w]);
        red[0] = m;
    }
    __syncthreads();
    const float m = red[0];
    __syncthreads();

    float lsum = 0.0f;
#pragma unroll
    for (int t = 0; t < 4; ++t) {
        int j = tid + t * 256;
        if (j < L) { r[t] = __expf((r[t] - m) * 0.125f); lsum += r[t]; }
        else         r[t] = 0.0f;
    }
    for (int o = 16; o; o >>= 1) lsum += __shfl_xor_sync(0xffffffffu, lsum, o);
    if ((tid & 31) == 0) red[tid >> 5] = lsum;
    __syncthreads();
    if (tid == 0) {
        float s = red[0];
#pragma unroll
        for (int w = 1; w < 8; ++w) s += red[w];
        red[0] = s;
    }
    __syncthreads();
    const float inv = 1.0f / red[0];
#pragma unroll
    for (int t = 0; t < 4; ++t) {
        int j = tid + t * 256;
        row[j] = r[t] * inv;
    }
}

// ---------------------------------------------------------------------------
extern "C" void kernel_launch(void* const* d_in, const int* in_sizes, int n_in,
                              void* d_out, int out_size)
{
    (void)in_sizes; (void)n_in; (void)out_size;
    const float* k  = (const float*)d_in[0];
    const float* v  = (const float*)d_in[1];
    const float* q  = (const float*)d_in[2];
    const float* Wk = (const float*)d_in[4];
    const float* Wq = (const float*)d_in[5];
    const float* Wv = (const float*)d_in[6];
    const float* Wo = (const float*)d_in[7];
    const float* bo = (const float*)d_in[8];
    float* out = (float*)d_out;

    float *Pq, *Pk, *Pv, *PvT, *Em, *F;
    cudaGetSymbolAddress((void**)&Pq,  g_Pq);
    cudaGetSymbolAddress((void**)&Pk,  g_Pk);
    cudaGetSymbolAddress((void**)&Pv,  g_Pv);
    cudaGetSymbolAddress((void**)&PvT, g_PvT);
    cudaGetSymbolAddress((void**)&Em,  g_E);
    cudaGetSymbolAddress((void**)&F,   g_F);

    dim3 blk(256);

    // Fused projections (bf16x3)
    dim3 gp(HE / BN, MQ / BM, 3);
    k_proj3<<<gp, blk>>>(q, k, v, Wq, Wk, Wv, Pq, Pk, Pv);

    // Pv -> PvT transpose
    dim3 gt(SS / 32, EE / 32, BB * HH);
    k_transp<<<gt, blk>>>(Pv, PvT);

    // Energy per (b,h), causal skip (bf16x3)
    dim3 ge(SS / BN, SS / BM, BB * HH);
    k_energy<<<ge, blk>>>(Pq, Pk, Em);

    k_softmax<<<dim3(SS, BB * HH), 256>>>(Em);

    // P @ V via PvT (tf32 NT, K trimmed causally)
    dim3 gv(EE / BN, SS / BM, BB * HH);
    k_pv<<<gv, blk>>>(Em, PvT, F);

    // Output projection + bias (tf32 NT)
    dim3 go(EE / BN, MQ / BM);
    k_outp<<<go, blk>>>(F, Wo, out, bo);
}

// round 17
// speedup vs baseline: 1.3241x; 1.0387x over previous
#include <cuda_runtime.h>
#include <cuda_bf16.h>
#include <cstdint>

#define BB 8
#define SS 1024
#define EE 512
#define HH 8
#define HE 4096
#define MQ 8192

#define BM 128
#define BN 128
#define PAD 20

__device__ float g_Pq [(size_t)MQ * HE];
__device__ float g_Pk [(size_t)MQ * HE];
__device__ float g_Pv [(size_t)MQ * HE];
__device__ float g_PvT[(size_t)MQ * HE];      // [bh][e][s] (raw-view slices)
__device__ float g_E  [(size_t)BB * HH * SS * SS];
__device__ float g_F  [(size_t)MQ * HE];

__device__ __forceinline__ uint32_t pk2(__nv_bfloat16 a, __nv_bfloat16 b) {
    return ((uint32_t)__bfloat16_as_ushort(b) << 16) | (uint32_t)__bfloat16_as_ushort(a);
}
__device__ __forceinline__ void split4(float4 v, uint2& hi, uint2& lo) {
    __nv_bfloat16 hx = __float2bfloat16(v.x), hy = __float2bfloat16(v.y);
    __nv_bfloat16 hz = __float2bfloat16(v.z), hw = __float2bfloat16(v.w);
    __nv_bfloat16 lx = __float2bfloat16(v.x - __bfloat162float(hx));
    __nv_bfloat16 ly = __float2bfloat16(v.y - __bfloat162float(hy));
    __nv_bfloat16 lz = __float2bfloat16(v.z - __bfloat162float(hz));
    __nv_bfloat16 lw = __float2bfloat16(v.w - __bfloat162float(hw));
    hi.x = pk2(hx, hy); hi.y = pk2(hz, hw);
    lo.x = pk2(lx, ly); lo.y = pk2(lz, lw);
}
__device__ __forceinline__ uint32_t f2tf(float x) {
    uint32_t r;
    asm("cvt.rna.tf32.f32 %0, %1;" : "=r"(r) : "f"(x));
    return r;
}

#define MMA16(acc, a, b) \
    asm volatile("mma.sync.aligned.m16n8k16.row.col.f32.bf16.bf16.f32 " \
        "{%0,%1,%2,%3},{%4,%5,%6,%7},{%8,%9},{%0,%1,%2,%3};" \
        : "+f"((acc)[0]), "+f"((acc)[1]), "+f"((acc)[2]), "+f"((acc)[3]) \
        : "r"((a)[0]), "r"((a)[1]), "r"((a)[2]), "r"((a)[3]), \
          "r"((b)[0]), "r"((b)[1]))

// ===========================================================================
// bf16x3 tile (R8-proven, NT): C = A @ B^T
// ===========================================================================
__device__ __forceinline__ void mma_bf3(
    const float* __restrict__ A, int lda,
    const float* __restrict__ B, int ldb,
    float* __restrict__ C, int ldc,
    int K, int m0, int n0)
{
    __shared__ uint32_t AsH[4][BM * 8], AsL[4][BM * 8];
    __shared__ uint32_t BsH[4][BN * 8], BsL[4][BN * 8];

    const int tid  = threadIdx.x;
    const int wid  = tid >> 5;
    const int lane = tid & 31;
    const int wm   = wid & 1;
    const int wn   = wid >> 1;
    const int qr   = lane >> 2;
    const int qc   = lane & 3;
    const int swz  = qr & 4;

    const int arow = tid >> 2;
    const int ak4  = tid & 3;

    float acc[4][4][4];
#pragma unroll
    for (int i = 0; i < 4; ++i)
#pragma unroll
        for (int j = 0; j < 4; ++j)
#pragma unroll
            for (int r = 0; r < 4; ++r) acc[i][j][r] = 0.0f;

    float4 ar0, ar1, br0, br1;

    auto load_g = [&](int k0) {
        const float* ap = A + (size_t)(m0 + arow) * lda + k0 + ak4 * 4;
        ar0 = *(const float4*)ap;
        ar1 = *(const float4*)(ap + (size_t)64 * lda);
        const float* bp = B + (size_t)(n0 + arow) * ldb + k0 + ak4 * 4;
        br0 = *(const float4*)bp;
        br1 = *(const float4*)(bp + (size_t)64 * ldb);
    };

    auto store_s = [&](int bu) {
        uint2 hi, lo;
        const int w0  = (ak4 * 2) ^ ((arow & 4) ? 4 : 0);
        const int w0b = (ak4 * 2) ^ (((arow + 64) & 4) ? 4 : 0);
        split4(ar0, hi, lo);
        *(uint2*)&AsH[bu][arow * 8 + w0] = hi;
        *(uint2*)&AsL[bu][arow * 8 + w0] = lo;
        split4(ar1, hi, lo);
        *(uint2*)&AsH[bu][(arow + 64) * 8 + w0b] = hi;
        *(uint2*)&AsL[bu][(arow + 64) * 8 + w0b] = lo;
        split4(br0, hi, lo);
        *(uint2*)&BsH[bu][arow * 8 + w0] = hi;
        *(uint2*)&BsL[bu][arow * 8 + w0] = lo;
        split4(br1, hi, lo);
        *(uint2*)&BsH[bu][(arow + 64) * 8 + w0b] = hi;
        *(uint2*)&BsL[bu][(arow + 64) * 8 + w0b] = lo;
    };

    auto compute = [&](int bu) {
        const int wA = qc ^ swz, wA2 = (qc + 4) ^ swz;
        uint32_t bh[4][2], bl[4][2];
#pragma unroll
        for (int nt = 0; nt < 4; ++nt) {
            int rb = (wn * 32 + nt * 8 + qr) * 8;
            bh[nt][0] = BsH[bu][rb + wA];  bh[nt][1] = BsH[bu][rb + wA2];
            bl[nt][0] = BsL[bu][rb + wA];  bl[nt][1] = BsL[bu][rb + wA2];
        }
        {
            uint32_t a[4][4];
#pragma unroll
            for (int mt = 0; mt < 4; ++mt) {
                int ra = (wm * 64 + mt * 16 + qr) * 8;
                a[mt][0] = AsH[bu][ra + wA];   a[mt][1] = AsH[bu][ra + 64 + wA];
                a[mt][2] = AsH[bu][ra + wA2];  a[mt][3] = AsH[bu][ra + 64 + wA2];
            }
#pragma unroll
            for (int mt = 0; mt < 4; ++mt)
#pragma unroll
                for (int nt = 0; nt < 4; ++nt) {
                    MMA16(acc[mt][nt], a[mt], bh[nt]);
                    MMA16(acc[mt][nt], a[mt], bl[nt]);
                }
        }
        {
            uint32_t a[4][4];
#pragma unroll
            for (int mt = 0; mt < 4; ++mt) {
                int ra = (wm * 64 + mt * 16 + qr) * 8;
                a[mt][0] = AsL[bu][ra + wA];   a[mt][1] = AsL[bu][ra + 64 + wA];
                a[mt][2] = AsL[bu][ra + wA2];  a[mt][3] = AsL[bu][ra + 64 + wA2];
            }
#pragma unroll
            for (int mt = 0; mt < 4; ++mt)
#pragma unroll
                for (int nt = 0; nt < 4; ++nt)
                    MMA16(acc[mt][nt], a[mt], bh[nt]);
        }
    };

    const int nkc = K >> 5;
    load_g(0);  store_s(0);
    load_g(16); store_s(1);
    __syncthreads();
    for (int kc = 1; kc < nkc; ++kc) {
        const int st = (kc & 1) * 2;
        const int pv = ((kc - 1) & 1) * 2;
        load_g(kc * 32);
        compute(pv);
        store_s(st);
        load_g(kc * 32 + 16);
        compute(pv + 1);
        store_s(st + 1);
        __syncthreads();
    }
    const int lp = ((nkc - 1) & 1) * 2;
    compute(lp);
    compute(lp + 1);

#pragma unroll
    for (int mt = 0; mt < 4; ++mt)
#pragma unroll
        for (int nt = 0; nt < 4; ++nt) {
            int row = m0 + wm * 64 + mt * 16 + qr;
            int col = n0 + wn * 32 + nt * 8 + qc * 2;
            float2 v0, v1;
            v0.x = acc[mt][nt][0]; v0.y = acc[mt][nt][1];
            v1.x = acc[mt][nt][2]; v1.y = acc[mt][nt][3];
            *(float2*)&C[(size_t)row * ldc + col] = v0;
            *(float2*)&C[(size_t)(row + 8) * ldc + col] = v1;
        }
}

// ===========================================================================
// tf32 single-pass tile (NT): C = A @ B^T
// ===========================================================================
template<bool HASBIAS>
__device__ __forceinline__ void mma_tf32(
    const float* __restrict__ A, int lda,
    const float* __restrict__ B, int ldb,
    float* __restrict__ C, int ldc,
    int K, int m0, int n0, const float* __restrict__ bias)
{
    __shared__ uint32_t As[2][BM * PAD];
    __shared__ uint32_t Bs[2][BN * PAD];

    const int tid  = threadIdx.x;
    const int wid  = tid >> 5;
    const int lane = tid & 31;
    const int wm   = wid & 1;
    const int wn   = wid >> 1;
    const int qr   = lane >> 2;
    const int qc   = lane & 3;

    const int arow = tid >> 2;
    const int ak4  = tid & 3;

    float acc[4][4][4];
#pragma unroll
    for (int i = 0; i < 4; ++i)
#pragma unroll
        for (int j = 0; j < 4; ++j)
#pragma unroll
            for (int r = 0; r < 4; ++r) acc[i][j][r] = 0.0f;

    float4 ar0, ar1, br0, br1;

    auto load_g = [&](int k0) {
        const float* ap = A + (size_t)(m0 + arow) * lda + k0 + ak4 * 4;
        ar0 = *(const float4*)ap;
        ar1 = *(const float4*)(ap + (size_t)64 * lda);
        const float* bp = B + (size_t)(n0 + arow) * ldb + k0 + ak4 * 4;
        br0 = *(const float4*)bp;
        br1 = *(const float4*)(bp + (size_t)64 * ldb);
    };

    auto store_s = [&](int st) {
        uint32_t* as = As[st];
        uint32_t* bs = Bs[st];
        uint4 v;
        v.x = f2tf(ar0.x); v.y = f2tf(ar0.y); v.z = f2tf(ar0.z); v.w = f2tf(ar0.w);
        *(uint4*)&as[arow * PAD + ak4 * 4] = v;
        v.x = f2tf(ar1.x); v.y = f2tf(ar1.y); v.z = f2tf(ar1.z); v.w = f2tf(ar1.w);
        *(uint4*)&as[(arow + 64) * PAD + ak4 * 4] = v;
        v.x = f2tf(br0.x); v.y = f2tf(br0.y); v.z = f2tf(br0.z); v.w = f2tf(br0.w);
        *(uint4*)&bs[arow * PAD + ak4 * 4] = v;
        v.x = f2tf(br1.x); v.y = f2tf(br1.y); v.z = f2tf(br1.z); v.w = f2tf(br1.w);
        *(uint4*)&bs[(arow + 64) * PAD + ak4 * 4] = v;
    };

    auto compute = [&](int st) {
        const uint32_t* as = As[st];
        const uint32_t* bs = Bs[st];
#pragma unroll
        for (int s = 0; s < 2; ++s) {
            uint32_t af[4][4], bf[4][2];
#pragma unroll
            for (int mt = 0; mt < 4; ++mt) {
                int base = (wm * 64 + mt * 16 + qr) * PAD + s * 8 + qc;
                af[mt][0] = as[base];
                af[mt][1] = as[base + 8 * PAD];
                af[mt][2] = as[base + 4];
                af[mt][3] = as[base + 8 * PAD + 4];
            }
#pragma unroll
            for (int nt = 0; nt < 4; ++nt) {
                int base = (wn * 32 + nt * 8 + qr) * PAD + s * 8 + qc;
                bf[nt][0] = bs[base];
                bf[nt][1] = bs[base + 4];
            }
#pragma unroll
            for (int mt = 0; mt < 4; ++mt)
#pragma unroll
                for (int nt = 0; nt < 4; ++nt)
                    asm volatile(
                        "mma.sync.aligned.m16n8k8.row.col.f32.tf32.tf32.f32 "
                        "{%0,%1,%2,%3}, {%4,%5,%6,%7}, {%8,%9}, {%0,%1,%2,%3};\n"
                        : "+f"(acc[mt][nt][0]), "+f"(acc[mt][nt][1]),
                          "+f"(acc[mt][nt][2]), "+f"(acc[mt][nt][3])
                        : "r"(af[mt][0]), "r"(af[mt][1]),
                          "r"(af[mt][2]), "r"(af[mt][3]),
                          "r"(bf[nt][0]), "r"(bf[nt][1]));
        }
    };

    const int niter = K >> 4;
    load_g(0);
    store_s(0);
    __syncthreads();
    for (int kt = 1; kt < niter; ++kt) {
        load_g(kt * 16);
        compute((kt - 1) & 1);
        store_s(kt & 1);
        __syncthreads();
    }
    compute((niter - 1) & 1);

#pragma unroll
    for (int mt = 0; mt < 4; ++mt)
#pragma unroll
        for (int nt = 0; nt < 4; ++nt) {
            int row = m0 + wm * 64 + mt * 16 + qr;
            int col = n0 + wn * 32 + nt * 8 + qc * 2;
            float2 v0, v1;
            v0.x = acc[mt][nt][0]; v0.y = acc[mt][nt][1];
            v1.x = acc[mt][nt][2]; v1.y = acc[mt][nt][3];
            if (HASBIAS) {
                v0.x += bias[col]; v0.y += bias[col + 1];
                v1.x += bias[col]; v1.y += bias[col + 1];
            }
            *(float2*)&C[(size_t)row * ldc + col] = v0;
            *(float2*)&C[(size_t)(row + 8) * ldc + col] = v1;
        }
}

// ---------------------------------------------------------------------------
// Kernels
// ---------------------------------------------------------------------------
// Q/K projections (bf16x3, precision-critical)
__global__ void __launch_bounds__(256, 2)
k_proj2(const float* __restrict__ q, const float* __restrict__ k,
        const float* __restrict__ Wq, const float* __restrict__ Wk,
        float* __restrict__ Pq, float* __restrict__ Pk)
{
    const float* A; const float* B; float* C;
    if (blockIdx.z == 0) { A = q; B = Wq; C = Pq; }
    else                 { A = k; B = Wk; C = Pk; }
    mma_bf3(A, EE, B, EE, C, HE, EE, blockIdx.y * BM, blockIdx.x * BN);
}

// V projection, full [MQ][HE] matrix (tf32 — post-softmax consumer only)
__global__ void __launch_bounds__(256, 2)
k_projv(const float* __restrict__ v, const float* __restrict__ Wv,
        float* __restrict__ Pv)
{
    mma_tf32<false>(v, EE, Wv, EE, Pv, HE, EE,
                    blockIdx.y * BM, blockIdx.x * BN, nullptr);
}

// Transpose raw-view slice: Pv flat [bh][s][e] -> PvT [bh][e][s] (R14-proven)
__global__ void __launch_bounds__(256)
k_transp(const float* __restrict__ Pv, float* __restrict__ PvT)
{
    __shared__ float t[32][33];
    const int bh = blockIdx.z;
    const int s0 = blockIdx.x * 32;
    const int e0 = blockIdx.y * 32;
    const int tx = threadIdx.x & 31;
    const int ty = threadIdx.x >> 5;
    const float* src = Pv  + (size_t)bh * SS * EE;
    float*       dst = PvT + (size_t)bh * EE * SS;
#pragma unroll
    for (int i = 0; i < 4; ++i)
        t[ty + i * 8][tx] = src[(size_t)(s0 + ty + i * 8) * EE + e0 + tx];
    __syncthreads();
#pragma unroll
    for (int i = 0; i < 4; ++i)
        dst[(size_t)(e0 + ty + i * 8) * SS + s0 + tx] = t[tx][ty + i * 8];
}

__global__ void __launch_bounds__(256, 2)
k_energy(const float* __restrict__ Pq, const float* __restrict__ Pk,
         float* __restrict__ Eng)
{
    const int bh = blockIdx.z;
    const int m0 = blockIdx.y * BM;
    const int n0 = blockIdx.x * BN;
    if (n0 > m0) return;
    mma_bf3(Pq + (size_t)bh * SS * EE, EE,
            Pk + (size_t)bh * SS * EE, EE,
            Eng + (size_t)bh * SS * SS, SS, EE, m0, n0);
}

__global__ void __launch_bounds__(256, 2)
k_pv(const float* __restrict__ P, const float* __restrict__ PvT,
     float* __restrict__ F)
{
    const int bh = blockIdx.z;
    const int b  = bh >> 3;
    const int h  = bh & 7;
    const int m0 = blockIdx.y * BM;
    const int n0 = blockIdx.x * BN;
    mma_tf32<false>(P + (size_t)bh * SS * SS, SS,
                    PvT + (size_t)bh * EE * SS, SS,
                    F + (size_t)b * SS * HE + (size_t)h * EE, HE,
                    m0 + BM, m0, n0, nullptr);
}

__global__ void __launch_bounds__(256, 2)
k_outp(const float* __restrict__ F, const float* __restrict__ Wo,
       float* __restrict__ C, const float* __restrict__ bias)
{
    mma_tf32<true>(F, HE, Wo, HE, C, EE, HE,
                   blockIdx.y * BM, blockIdx.x * BN, bias);
}

// Causal softmax, in-place, mask-before-scale (scale = 1/8)
__global__ void k_softmax(float* __restrict__ Eng)
{
    const int i = blockIdx.x;
    float* row = Eng + ((size_t)blockIdx.y * SS + i) * SS;
    const int L = i + 1;
    const int tid = threadIdx.x;

    float r[4];
    float lmax = -1e30f;
#pragma unroll
    for (int t = 0; t < 4; ++t) {
        int j = tid + t * 256;
        if (j < L) { r[t] = row[j]; lmax = fmaxf(lmax, r[t]); }
        else         r[t] = -1e30f;
    }
    __shared__ float red[8];
    for (int o = 16; o; o >>= 1) lmax = fmaxf(lmax, __shfl_xor_sync(0xffffffffu, lmax, o));
    if ((tid & 31) == 0) red[tid >> 5] = lmax;
    __syncthreads();
    if (tid == 0) {
        float m = red[0];
#pragma unroll
        for (int w = 1; w < 8; ++w) m = fmaxf(m, red[w]);
        red[0] = m;
    }
    __syncthreads();
    const float m = red[0];
    __syncthreads();

    float lsum = 0.0f;
#pragma unroll
    for (int t = 0; t < 4; ++t) {
        int j = tid + t * 256;
        if (j < L) { r[t] = __expf((r[t] - m) * 0.125f); lsum += r[t]; }
        else         r[t] = 0.0f;
    }
    for (int o = 16; o; o >>= 1) lsum += __shfl_xor_sync(0xffffffffu, lsum, o);
    if ((tid & 31) == 0) red[tid >> 5] = lsum;
    __syncthreads();
    if (tid == 0) {
        float s = red[0];
#pragma unroll
        for (int w = 1; w < 8; ++w) s += red[w];
        red[0] = s;
    }
    __syncthreads();
    const float inv = 1.0f / red[0];
#pragma unroll
    for (int t = 0; t < 4; ++t) {
        int j = tid + t * 256;
        row[j] = r[t] * inv;
    }
}

// ---------------------------------------------------------------------------
extern "C" void kernel_launch(void* const* d_in, const int* in_sizes, int n_in,
                              void* d_out, int out_size)
{
    (void)in_sizes; (void)n_in; (void)out_size;
    const float* k  = (const float*)d_in[0];
    const float* v  = (const float*)d_in[1];
    const float* q  = (const float*)d_in[2];
    const float* Wk = (const float*)d_in[4];
    const float* Wq = (const float*)d_in[5];
    const float* Wv = (const float*)d_in[6];
    const float* Wo = (const float*)d_in[7];
    const float* bo = (const float*)d_in[8];
    float* out = (float*)d_out;

    float *Pq, *Pk, *Pv, *PvT, *Em, *F;
    cudaGetSymbolAddress((void**)&Pq,  g_Pq);
    cudaGetSymbolAddress((void**)&Pk,  g_Pk);
    cudaGetSymbolAddress((void**)&Pv,  g_Pv);
    cudaGetSymbolAddress((void**)&PvT, g_PvT);
    cudaGetSymbolAddress((void**)&Em,  g_E);
    cudaGetSymbolAddress((void**)&F,   g_F);

    dim3 blk(256);

    // Q/K projections (bf16x3)
    dim3 gp(HE / BN, MQ / BM, 2);
    k_proj2<<<gp, blk>>>(q, k, Wq, Wk, Pq, Pk);

    // V projection (tf32, full matrix)
    dim3 gpv(HE / BN, MQ / BM);
    k_projv<<<gpv, blk>>>(v, Wv, Pv);

    // Pv -> PvT transpose (raw-view slices)
    dim3 gt(SS / 32, EE / 32, BB * HH);
    k_transp<<<gt, blk>>>(Pv, PvT);

    // Energy per (b,h), causal skip (bf16x3)
    dim3 ge(SS / BN, SS / BM, BB * HH);
    k_energy<<<ge, blk>>>(Pq, Pk, Em);

    k_softmax<<<dim3(SS, BB * HH), 256>>>(Em);

    // P @ V via PvT (tf32 NT, K trimmed causally)
    dim3 gv(EE / BN, SS / BM, BB * HH);
    k_pv<<<gv, blk>>>(Em, PvT, F);

    // Output projection + bias (tf32 NT)
    dim3 go(EE / BN, MQ / BM);
    k_outp<<<go, blk>>>(F, Wo, out, bo);
}